// round 8
// baseline (speedup 1.0000x reference)
#include <cuda_runtime.h>
#include <cuda_fp16.h>
#include <cstdint>

// RNN-T Joiner, fp16 tensor-core path. R8: f16-accumulator HMMA experiment.
//   prep_a: A_half[m,k] = fp16(tanh(src+tgt))     (164 MB scratch)
//   prep_w: W -> fp16                              (1 MB scratch)
//   gemm:   per chunk (k=32): 2 chained mma m16n8k16 with f16 accum,
//           then promote to fp32 accumulators. 4-stage cp.async + ldmatrix.
// M = 160000, K = 512, N = 1024.

constexpr int Bb = 4, Tt = 400, Uu = 100, Dd = 512, Vv = 1024;
constexpr long long Mm = (long long)Bb * Tt * Uu;   // 160000 = 128*1250

#define BM 128
#define BN 128
#define BK 32
#define NCH (Dd / BK)        // 16
#define STG 4                // cp.async stages
#define RST 40               // smem row stride in halfs (80B): conflict-free

__device__ __half A_half[(size_t)Mm * Dd];   // 164 MB scratch (sanctioned)
__device__ __half W_half[(size_t)Vv * Dd];   // 1 MB

__device__ __forceinline__ float fast_tanh(float x) {
    float y; asm("tanh.approx.f32 %0, %1;" : "=f"(y) : "f"(x)); return y;
}
__device__ __forceinline__ uint32_t smem_u32(const void* p) {
    uint32_t a;
    asm("{ .reg .u64 t; cvta.to.shared.u64 t, %1; cvt.u32.u64 %0, t; }" : "=r"(a) : "l"(p));
    return a;
}
// f16-accumulate mma: D(f16x4) = A*B + C(f16x4)
__device__ __forceinline__ void mma_acc16(uint32_t& d0, uint32_t& d1,
                                          const uint32_t* a, uint32_t b0, uint32_t b1,
                                          uint32_t c0, uint32_t c1) {
    asm volatile(
        "mma.sync.aligned.m16n8k16.row.col.f16.f16.f16.f16 "
        "{%0,%1}, {%2,%3,%4,%5}, {%6,%7}, {%8,%9};"
        : "=r"(d0), "=r"(d1)
        : "r"(a[0]), "r"(a[1]), "r"(a[2]), "r"(a[3]),
          "r"(b0), "r"(b1), "r"(c0), "r"(c1));
}
__device__ __forceinline__ void ldm_x4(uint32_t* r, uint32_t addr) {
    asm volatile("ldmatrix.sync.aligned.m8n8.x4.shared.b16 {%0,%1,%2,%3}, [%4];"
                 : "=r"(r[0]), "=r"(r[1]), "=r"(r[2]), "=r"(r[3]) : "r"(addr));
}

// ---------------- Phase 1a: A = fp16(tanh(src + tgt)) ----------------
__global__ __launch_bounds__(256)
void prep_a_kernel(const float* __restrict__ src, const float* __restrict__ tgt) {
    size_t idx = (size_t)blockIdx.x * 256 + threadIdx.x;   // one per 8 elems
    int m = (int)(idx >> 6);
    int kv = ((int)idx & 63) * 8;
    int b = m / (Tt * Uu);
    int rem = m - b * (Tt * Uu);
    int t = rem / Uu;
    int u = rem - t * Uu;
    const float* sp = src + ((size_t)b * Tt + t) * Dd + kv;
    const float* tp = tgt + ((size_t)b * Uu + u) * Dd + kv;
    float4 s0 = *reinterpret_cast<const float4*>(sp);
    float4 s1 = *reinterpret_cast<const float4*>(sp + 4);
    float4 t0 = *reinterpret_cast<const float4*>(tp);
    float4 t1 = *reinterpret_cast<const float4*>(tp + 4);
    __half2 h[4];
    h[0] = __floats2half2_rn(fast_tanh(s0.x + t0.x), fast_tanh(s0.y + t0.y));
    h[1] = __floats2half2_rn(fast_tanh(s0.z + t0.z), fast_tanh(s0.w + t0.w));
    h[2] = __floats2half2_rn(fast_tanh(s1.x + t1.x), fast_tanh(s1.y + t1.y));
    h[3] = __floats2half2_rn(fast_tanh(s1.z + t1.z), fast_tanh(s1.w + t1.w));
    *reinterpret_cast<uint4*>(&A_half[(size_t)m * Dd + kv]) =
        *reinterpret_cast<uint4*>(h);
}

// ---------------- Phase 1b: W -> fp16 ----------------
__global__ __launch_bounds__(256)
void prep_w_kernel(const float* __restrict__ W) {
    size_t idx = ((size_t)blockIdx.x * 256 + threadIdx.x) * 8;
    float4 w0 = *reinterpret_cast<const float4*>(W + idx);
    float4 w1 = *reinterpret_cast<const float4*>(W + idx + 4);
    __half2 h[4];
    h[0] = __floats2half2_rn(w0.x, w0.y);
    h[1] = __floats2half2_rn(w0.z, w0.w);
    h[2] = __floats2half2_rn(w1.x, w1.y);
    h[3] = __floats2half2_rn(w1.z, w1.w);
    *reinterpret_cast<uint4*>(&W_half[idx]) = *reinterpret_cast<uint4*>(h);
}

// ---------------- Phase 2: fp16 GEMM, f16 accum per chunk ----------------
constexpr int STAGE_H = BM * RST;                   // 5120 halfs / stage
constexpr int SMEM_TOTAL = 2 * STG * STAGE_H * 2;   // A + B = 81920 B

__global__ __launch_bounds__(256, 2)
void joiner_gemm_fp16(const float* __restrict__ bias, float* __restrict__ out) {
    extern __shared__ __half sm[];
    __half* Asm = sm;
    __half* Bsm = sm + STG * STAGE_H;

    const int tid = threadIdx.x;
    const int wid = tid >> 5, lid = tid & 31;
    const int g = lid >> 2, c = lid & 3;
    const int wm = wid >> 2, wn = wid & 3;           // warp grid 2(m) x 4(n)
    // n-block fastest -> 8 CTAs share one A m-chunk in L2
    const size_t m0 = (size_t)blockIdx.y * BM;
    const int n0 = blockIdx.x * BN;

    // producer mapping: 2 threads per row, 16 halfs (32B) each
    const int r = tid >> 1;
    const int h = tid & 1;
    const __half* agp = A_half + (m0 + r) * Dd + h * 16;
    const __half* bgp = W_half + (size_t)(n0 + r) * Dd + h * 16;
    const uint32_t a_dst0 = smem_u32(Asm) + (uint32_t)(r * (RST * 2) + h * 32);
    const uint32_t b_dst0 = smem_u32(Bsm) + (uint32_t)(r * (RST * 2) + h * 32);

    // ldmatrix per-lane source addresses
    const uint32_t a_lm = smem_u32(Asm)
        + (uint32_t)((wm * 64 + (lid & 15)) * (RST * 2) + ((lid >> 4) & 1) * 16);
    const uint32_t b_lm = smem_u32(Bsm)
        + (uint32_t)((wn * 32 + ((lid >> 4) & 1) * 8 + (lid & 7)) * (RST * 2)
                     + ((lid >> 3) & 1) * 16);

    float acc[4][4][4];
#pragma unroll
    for (int mt = 0; mt < 4; mt++)
#pragma unroll
        for (int nt = 0; nt < 4; nt++)
#pragma unroll
            for (int i = 0; i < 4; i++) acc[mt][nt][i] = 0.0f;

#define ISSUE_STAGE(CH) do {                                                    \
        int st_ = (CH) & (STG - 1);                                             \
        const __half* ag_ = agp + (CH) * BK;                                    \
        const __half* bg_ = bgp + (CH) * BK;                                    \
        uint32_t ad_ = a_dst0 + st_ * (STAGE_H * 2);                            \
        uint32_t bd_ = b_dst0 + st_ * (STAGE_H * 2);                            \
        asm volatile(                                                           \
            "cp.async.cg.shared.global [%0], [%1], 16;\n"                       \
            "cp.async.cg.shared.global [%2], [%3], 16;\n"                       \
            "cp.async.cg.shared.global [%4], [%5], 16;\n"                       \
            "cp.async.cg.shared.global [%6], [%7], 16;\n"                       \
            "cp.async.commit_group;"                                            \
            :: "r"(ad_), "l"(ag_), "r"(ad_ + 16), "l"(ag_ + 8),                 \
               "r"(bd_), "l"(bg_), "r"(bd_ + 16), "l"(bg_ + 8) : "memory");     \
    } while (0)

    ISSUE_STAGE(0); ISSUE_STAGE(1); ISSUE_STAGE(2);

    for (int ch = 0; ch < NCH; ch++) {
        const int rem = NCH - 1 - ch;
        if (rem >= 2)      asm volatile("cp.async.wait_group 2;" ::: "memory");
        else if (rem == 1) asm volatile("cp.async.wait_group 1;" ::: "memory");
        else               asm volatile("cp.async.wait_group 0;" ::: "memory");
        __syncthreads();
        if (ch + 3 < NCH) ISSUE_STAGE(ch + 3);

        const int st = ch & (STG - 1);
        const uint32_t a_st = a_lm + st * (STAGE_H * 2);
        const uint32_t b_st = b_lm + st * (STAGE_H * 2);

        // B fragments for both k-steps (ks offset = 16 halfs = 32B)
        uint32_t bfr[2][2][4];
        ldm_x4(bfr[0][0], b_st);
        ldm_x4(bfr[0][1], b_st + 16 * (RST * 2));
        ldm_x4(bfr[1][0], b_st + 32);
        ldm_x4(bfr[1][1], b_st + 16 * (RST * 2) + 32);

#pragma unroll
        for (int mt = 0; mt < 4; mt++) {
            uint32_t a0[4], a1[4];
            ldm_x4(a0, a_st + mt * 16 * (RST * 2));
            ldm_x4(a1, a_st + mt * 16 * (RST * 2) + 32);
#pragma unroll
            for (int nt = 0; nt < 4; nt++) {
                const int gq = nt >> 1, pq = (nt & 1) * 2;
                uint32_t d0, d1;
                mma_acc16(d0, d1, a0, bfr[0][gq][pq], bfr[0][gq][pq + 1], 0u, 0u);
                mma_acc16(d0, d1, a1, bfr[1][gq][pq], bfr[1][gq][pq + 1], d0, d1);
                float2 p0 = __half22float2(*reinterpret_cast<__half2*>(&d0));
                float2 p1 = __half22float2(*reinterpret_cast<__half2*>(&d1));
                acc[mt][nt][0] += p0.x;
                acc[mt][nt][1] += p0.y;
                acc[mt][nt][2] += p1.x;
                acc[mt][nt][3] += p1.y;
            }
        }
    }

    // ---- epilogue: bias + float2 stores ----
#pragma unroll
    for (int nt = 0; nt < 4; nt++) {
        const int col = n0 + wn * 32 + nt * 8 + 2 * c;
        const float2 bz = *reinterpret_cast<const float2*>(bias + col);
#pragma unroll
        for (int mt = 0; mt < 4; mt++) {
            const size_t row = m0 + wm * 64 + mt * 16 + g;
            float2 o1, o2;
            o1.x = acc[mt][nt][0] + bz.x;
            o1.y = acc[mt][nt][1] + bz.y;
            o2.x = acc[mt][nt][2] + bz.x;
            o2.y = acc[mt][nt][3] + bz.y;
            *reinterpret_cast<float2*>(out + row * Vv + col) = o1;
            *reinterpret_cast<float2*>(out + (row + 8) * Vv + col) = o2;
        }
    }
}

// Defensive tail: append lengths if harness packs the whole tuple.
__global__ void joiner_tail_kernel(const int* __restrict__ src_len,
                                   const int* __restrict__ tgt_len,
                                   float* __restrict__ out, int extras) {
    int i = threadIdx.x;
    if (i < extras) {
        size_t base = (size_t)Mm * Vv;
        if (i < Bb) out[base + i] = (float)src_len[i];
        else if (i < 2 * Bb) out[base + i] = (float)tgt_len[i - Bb];
        else out[base + i] = 0.0f;
    }
}

extern "C" void kernel_launch(void* const* d_in, const int* in_sizes, int n_in,
                              void* d_out, int out_size) {
    const float* src     = (const float*)d_in[0];
    const int*   src_len = (const int*)d_in[1];
    const float* tgt     = (const float*)d_in[2];
    const int*   tgt_len = (const int*)d_in[3];
    const float* W       = (const float*)d_in[4];
    const float* bias    = (const float*)d_in[5];
    float* out = (float*)d_out;

    prep_a_kernel<<<(unsigned)(Mm * (Dd / 8) / 256), 256>>>(src, tgt);
    prep_w_kernel<<<(Vv * Dd / 8) / 256, 256>>>(W);

    cudaFuncSetAttribute(joiner_gemm_fp16,
                         cudaFuncAttributeMaxDynamicSharedMemorySize, SMEM_TOTAL);
    dim3 grid(Vv / BN, (unsigned)(Mm / BM));   // 8 x 1250, n fastest
    joiner_gemm_fp16<<<grid, 256, SMEM_TOTAL>>>(bias, out);

    long long extras = (long long)out_size - (long long)Mm * Vv;
    if (extras > 0) {
        int e = (int)(extras > 64 ? 64 : extras);
        joiner_tail_kernel<<<1, 64>>>(src_len, tgt_len, out, e);
    }
}